// round 2
// baseline (speedup 1.0000x reference)
#include <cuda_runtime.h>
#include <math.h>

#define NT 1000      // NUM_TEAMS
#define NV 3         // NUM_VENUES
#define NR 3         // NUM_RESULTS
#define H  128
#define B  1024
#define L  256
// W_out is (517, 3) row-major: rows 0:128 venue, 128:256 team, 256:384 opp,
// 384:512 result, 512 gf, 513 ga, 514:517 stats.

// Scratch (device globals — no allocation allowed)
__device__ float g_Gteam[NT * NT];   // team_embed @ team_embed^T
__device__ float g_Gven[NV * NV];    // venue Gram
__device__ float g_PT1[NT * 3];      // team_embed @ W[128:256]
__device__ float g_PT2[NT * 3];      // team_embed @ W[256:384]
__device__ float g_PV[NV * 3];       // venue_embed @ W[0:128]
__device__ float g_PR[NR * 3];       // result_embed @ W[384:512]

// ---------------------------------------------------------------------------
// Kernel 1: team Gram matrix, 32x32 tiles, K=128
// ---------------------------------------------------------------------------
__global__ void gram_kernel(const float* __restrict__ E) {
    __shared__ float As[32 * 129];
    __shared__ float Bs[32 * 129];
    const int tx = threadIdx.x;         // 0..31 (j)
    const int ty = threadIdx.y;         // 0..31 (i)
    const int tid = ty * 32 + tx;       // 0..1023
    const int i0 = blockIdx.y * 32;
    const int j0 = blockIdx.x * 32;

    // cooperative load of both 32x128 tiles (zero-pad out of range)
    #pragma unroll
    for (int idx = tid; idx < 32 * 128; idx += 1024) {
        const int r = idx >> 7;
        const int k = idx & 127;
        const int ri = i0 + r;
        const int rj = j0 + r;
        As[r * 129 + k] = (ri < NT) ? E[ri * H + k] : 0.0f;
        Bs[r * 129 + k] = (rj < NT) ? E[rj * H + k] : 0.0f;
    }
    __syncthreads();

    float acc = 0.0f;
    #pragma unroll 8
    for (int k = 0; k < 128; k++) {
        acc += As[ty * 129 + k] * Bs[tx * 129 + k];
    }
    const int i = i0 + ty;
    const int j = j0 + tx;
    if (i < NT && j < NT) g_Gteam[i * NT + j] = acc;
}

// ---------------------------------------------------------------------------
// Kernel 2: small projections (PT1, PT2, PV, PR, Gven)
// ---------------------------------------------------------------------------
__global__ void proj_kernel(const float* __restrict__ team_embed,
                            const float* __restrict__ venue_embed,
                            const float* __restrict__ result_embed,
                            const float* __restrict__ W) {
    const int t = blockIdx.x * blockDim.x + threadIdx.x;
    if (t < NT) {
        const float* row = team_embed + t * H;
        float a0 = 0, a1 = 0, a2 = 0, b0 = 0, b1 = 0, b2 = 0;
        #pragma unroll 4
        for (int k = 0; k < H; k++) {
            const float e = row[k];
            a0 += e * W[(128 + k) * 3 + 0];
            a1 += e * W[(128 + k) * 3 + 1];
            a2 += e * W[(128 + k) * 3 + 2];
            b0 += e * W[(256 + k) * 3 + 0];
            b1 += e * W[(256 + k) * 3 + 1];
            b2 += e * W[(256 + k) * 3 + 2];
        }
        g_PT1[t * 3 + 0] = a0; g_PT1[t * 3 + 1] = a1; g_PT1[t * 3 + 2] = a2;
        g_PT2[t * 3 + 0] = b0; g_PT2[t * 3 + 1] = b1; g_PT2[t * 3 + 2] = b2;
    }
    if (t < 9) {
        const int i = t / 3, j = t % 3;
        // venue Gram
        float g = 0;
        #pragma unroll 4
        for (int k = 0; k < H; k++)
            g += venue_embed[i * H + k] * venue_embed[j * H + k];
        g_Gven[t] = g;
        // PV[v][r] : venue_embed . W rows 0:128
        float pv = 0;
        #pragma unroll 4
        for (int k = 0; k < H; k++)
            pv += venue_embed[i * H + k] * W[k * 3 + j];
        g_PV[t] = pv;
        // PR[res][r] : result_embed . W rows 384:512
        float pr = 0;
        #pragma unroll 4
        for (int k = 0; k < H; k++)
            pr += result_embed[i * H + k] * W[(384 + k) * 3 + j];
        g_PR[t] = pr;
    }
}

// ---------------------------------------------------------------------------
// Kernel 3: main — softmax over L + weighted projected-contribution reduce
// One block per batch, one thread per sequence position.
// ---------------------------------------------------------------------------
__global__ void __launch_bounds__(L) main_kernel(
    const int* __restrict__ venue, const int* __restrict__ team,
    const int* __restrict__ opp,   const int* __restrict__ result,
    const float* __restrict__ gf,  const float* __restrict__ ga,
    const float* __restrict__ stats,
    const int* __restrict__ next_venue, const int* __restrict__ next_team,
    const int* __restrict__ next_opp,
    const float* __restrict__ W, const float* __restrict__ b_out,
    float* __restrict__ out) {

    const int b = blockIdx.x;
    const int l = threadIdx.x;
    const int idx = b * L + l;
    const int lane = l & 31, wid = l >> 5;

    const int nv = next_venue[b];
    const int nt = next_team[b];
    const int no = next_opp[b];

    const int v = venue[idx];
    const int t = team[idx];
    const int o = opp[idx];
    const int r = result[idx];
    const float gfv = gf[idx];
    const float gav = ga[idx];

    // score
    const float inv_scale = 0.05103103630798288f;  // 1/sqrt(384)
    float s = (g_Gven[v * 3 + nv] + g_Gteam[t * NT + nt] + g_Gteam[o * NT + no]) * inv_scale;

    __shared__ float sm_max[8];
    __shared__ float sm_sum[8];
    __shared__ float sm_c[8 * 3];

    // block max
    float m = s;
    #pragma unroll
    for (int off = 16; off; off >>= 1)
        m = fmaxf(m, __shfl_xor_sync(0xffffffffu, m, off));
    if (lane == 0) sm_max[wid] = m;
    __syncthreads();
    m = sm_max[0];
    #pragma unroll
    for (int w = 1; w < 8; w++) m = fmaxf(m, sm_max[w]);

    // exp + block sum
    float e = __expf(s - m);
    float su = e;
    #pragma unroll
    for (int off = 16; off; off >>= 1)
        su += __shfl_xor_sync(0xffffffffu, su, off);
    if (lane == 0) sm_sum[wid] = su;
    __syncthreads();
    float denom = sm_sum[0];
    #pragma unroll
    for (int w = 1; w < 8; w++) denom += sm_sum[w];
    const float a = e * __frcp_rn(denom);

    // projected contribution per result class, weighted by attn
    float c0 = a * (g_PV[v * 3 + 0] + g_PT1[t * 3 + 0] + g_PT2[o * 3 + 0] + g_PR[r * 3 + 0]
                    + gfv * W[512 * 3 + 0] + gav * W[513 * 3 + 0]);
    float c1 = a * (g_PV[v * 3 + 1] + g_PT1[t * 3 + 1] + g_PT2[o * 3 + 1] + g_PR[r * 3 + 1]
                    + gfv * W[512 * 3 + 1] + gav * W[513 * 3 + 1]);
    float c2 = a * (g_PV[v * 3 + 2] + g_PT1[t * 3 + 2] + g_PT2[o * 3 + 2] + g_PR[r * 3 + 2]
                    + gfv * W[512 * 3 + 2] + gav * W[513 * 3 + 2]);

    #pragma unroll
    for (int off = 16; off; off >>= 1) {
        c0 += __shfl_xor_sync(0xffffffffu, c0, off);
        c1 += __shfl_xor_sync(0xffffffffu, c1, off);
        c2 += __shfl_xor_sync(0xffffffffu, c2, off);
    }
    if (lane == 0) {
        sm_c[wid * 3 + 0] = c0;
        sm_c[wid * 3 + 1] = c1;
        sm_c[wid * 3 + 2] = c2;
    }
    __syncthreads();

    if (l == 0) {
        float L0 = 0, L1 = 0, L2 = 0;
        #pragma unroll
        for (int w = 0; w < 8; w++) {
            L0 += sm_c[w * 3 + 0];
            L1 += sm_c[w * 3 + 1];
            L2 += sm_c[w * 3 + 2];
        }
        const float s0 = stats[b * 3 + 0], s1 = stats[b * 3 + 1], s2 = stats[b * 3 + 2];
        L0 += s0 * W[514 * 3 + 0] + s1 * W[515 * 3 + 0] + s2 * W[516 * 3 + 0] + b_out[0];
        L1 += s0 * W[514 * 3 + 1] + s1 * W[515 * 3 + 1] + s2 * W[516 * 3 + 1] + b_out[1];
        L2 += s0 * W[514 * 3 + 2] + s1 * W[515 * 3 + 2] + s2 * W[516 * 3 + 2] + b_out[2];
        out[b * 3 + 0] = L0;
        out[b * 3 + 1] = L1;
        out[b * 3 + 2] = L2;
    }
}

// ---------------------------------------------------------------------------
extern "C" void kernel_launch(void* const* d_in, const int* in_sizes, int n_in,
                              void* d_out, int out_size) {
    const float* team_embed   = (const float*)d_in[0];
    const float* venue_embed  = (const float*)d_in[1];
    const float* result_embed = (const float*)d_in[2];
    const float* W_out        = (const float*)d_in[3];
    const float* b_out        = (const float*)d_in[4];
    const float* goals_for    = (const float*)d_in[5];
    const float* goals_against= (const float*)d_in[6];
    const float* stats        = (const float*)d_in[7];
    const int*   venue        = (const int*)d_in[8];
    const int*   team         = (const int*)d_in[9];
    const int*   opponent     = (const int*)d_in[10];
    const int*   result       = (const int*)d_in[11];
    const int*   next_venue   = (const int*)d_in[12];
    const int*   next_team    = (const int*)d_in[13];
    const int*   next_opponent= (const int*)d_in[14];
    float* out = (float*)d_out;

    dim3 gblk(32, 32);
    dim3 ggrid((NT + 31) / 32, (NT + 31) / 32);
    gram_kernel<<<ggrid, gblk>>>(team_embed);

    proj_kernel<<<4, 256>>>(team_embed, venue_embed, result_embed, W_out);

    main_kernel<<<B, L>>>(venue, team, opponent, result,
                          goals_for, goals_against, stats,
                          next_venue, next_team, next_opponent,
                          W_out, b_out, out);
}

// round 3
// speedup vs baseline: 1.7994x; 1.7994x over previous
#include <cuda_runtime.h>
#include <math.h>

#define NT   1000
#define NTP  1024      // padded teams
#define H    128
#define B    1024
#define L    256
// W_out (517,3) row-major: rows 0:128 venue, 128:256 team, 256:384 opp,
// 384:512 result, 512 gf, 513 ga, 514:517 stats.

// ---- device scratch (no allocation allowed) ----
__device__ float  g_Et[H * NTP];          // team_embed transposed [k][team], zero-padded
__device__ float  g_G[NTP * NTP];         // team Gram (padded)
__device__ float4 g_PT1[NTP];             // team_embed @ W[128:256]  (per class, .w unused)
__device__ float4 g_PT2[NTP];             // team_embed @ W[256:384]
__device__ float4 g_PVR[9];               // PV[v] + PR[r] fused table
__device__ float  g_Gven[9];              // venue Gram

// ---------------------------------------------------------------------------
// Kernel 0: transpose team_embed (blocks 0..127) + projections (blocks 128..131)
// ---------------------------------------------------------------------------
__global__ void __launch_bounds__(256) prep_kernel(
    const float* __restrict__ team_embed,
    const float* __restrict__ venue_embed,
    const float* __restrict__ result_embed,
    const float* __restrict__ W) {
    const int bx  = blockIdx.x;
    const int tid = threadIdx.x;

    if (bx < 128) {
        // 32x32 transpose tile: rows (teams) bi*32.., cols (k) bk*32..
        __shared__ float sm[32][33];
        const int bi = bx & 31;   // team tile 0..31 (covers 1024 padded rows)
        const int bk = bx >> 5;   // k tile 0..3
        const int tx = tid & 31;
        const int ty = tid >> 5;  // 0..7
        #pragma unroll
        for (int i = 0; i < 4; i++) {
            const int r = bi * 32 + ty + 8 * i;
            sm[ty + 8 * i][tx] = (r < NT) ? team_embed[r * H + bk * 32 + tx] : 0.0f;
        }
        __syncthreads();
        #pragma unroll
        for (int i = 0; i < 4; i++) {
            const int k = bk * 32 + ty + 8 * i;
            g_Et[k * NTP + bi * 32 + tx] = sm[tx][ty + 8 * i];
        }
        return;
    }

    // projection blocks: t = 0..1023
    const int t = (bx - 128) * 256 + tid;
    if (t < NT) {
        const float4* row = (const float4*)(team_embed + t * H);
        float a0 = 0, a1 = 0, a2 = 0, b0 = 0, b1 = 0, b2 = 0;
        #pragma unroll 8
        for (int k4 = 0; k4 < 32; k4++) {
            const float4 e = row[k4];
            const float ev[4] = {e.x, e.y, e.z, e.w};
            #pragma unroll
            for (int d = 0; d < 4; d++) {
                const int k = 4 * k4 + d;
                a0 += ev[d] * W[(128 + k) * 3 + 0];
                a1 += ev[d] * W[(128 + k) * 3 + 1];
                a2 += ev[d] * W[(128 + k) * 3 + 2];
                b0 += ev[d] * W[(256 + k) * 3 + 0];
                b1 += ev[d] * W[(256 + k) * 3 + 1];
                b2 += ev[d] * W[(256 + k) * 3 + 2];
            }
        }
        g_PT1[t] = make_float4(a0, a1, a2, 0.0f);
        g_PT2[t] = make_float4(b0, b1, b2, 0.0f);
    } else if (t >= NTP - 24 && t < NTP) {
        // nothing
    }
    if (bx == 128 && tid < 9) {
        const int v = tid / 3, r = tid % 3;
        // venue Gram (i=v, j=r reused as generic 3x3 indices)
        float g = 0;
        #pragma unroll 8
        for (int k = 0; k < H; k++)
            g += venue_embed[v * H + k] * venue_embed[r * H + k];
        g_Gven[tid] = g;
        // PVR[v][r][c] = venue_v . W[0:128,c] + result_r . W[384:512,c]
        float p0 = 0, p1 = 0, p2 = 0;
        #pragma unroll 8
        for (int k = 0; k < H; k++) {
            const float ve = venue_embed[v * H + k];
            const float re = result_embed[r * H + k];
            p0 += ve * W[k * 3 + 0] + re * W[(384 + k) * 3 + 0];
            p1 += ve * W[k * 3 + 1] + re * W[(384 + k) * 3 + 1];
            p2 += ve * W[k * 3 + 2] + re * W[(384 + k) * 3 + 2];
        }
        g_PVR[tid] = make_float4(p0, p1, p2, 0.0f);
    }
}

// ---------------------------------------------------------------------------
// Kernel 1: team Gram, 64x64 tile, 4x4 micro-tile, swizzled k-major smem
// ---------------------------------------------------------------------------
__global__ void __launch_bounds__(256) gram_kernel() {
    __shared__ float4 As4[64 * 16];   // [k][c^swz], teams i0+4c+u
    __shared__ float4 Bs4[64 * 16];
    const int tid = threadIdx.x;
    const int tx = tid & 15;          // j micro-group
    const int ty = tid >> 4;          // i micro-group
    const int i0 = blockIdx.y * 64;
    const int j0 = blockIdx.x * 64;

    float acc[4][4];
    #pragma unroll
    for (int u = 0; u < 4; u++)
        #pragma unroll
        for (int v = 0; v < 4; v++) acc[u][v] = 0.0f;

    const float4* Et4 = (const float4*)g_Et;

    for (int kb = 0; kb < 128; kb += 64) {
        __syncthreads();
        // load 64 k-rows x 16 float4 per tile; 4 float4 per thread per tile
        #pragma unroll
        for (int i = 0; i < 4; i++) {
            const int idx = tid + 256 * i;
            const int k = idx >> 4;         // 0..63
            const int c = idx & 15;
            const int sw = c ^ (k & 15);
            As4[k * 16 + sw] = Et4[(kb + k) * (NTP / 4) + (i0 >> 2) + c];
            Bs4[k * 16 + sw] = Et4[(kb + k) * (NTP / 4) + (j0 >> 2) + c];
        }
        __syncthreads();

        #pragma unroll 16
        for (int k = 0; k < 64; k++) {
            const float4 a4 = As4[k * 16 + (ty ^ (k & 15))];
            const float4 b4 = Bs4[k * 16 + (tx ^ (k & 15))];
            const float av[4] = {a4.x, a4.y, a4.z, a4.w};
            const float bv[4] = {b4.x, b4.y, b4.z, b4.w};
            #pragma unroll
            for (int u = 0; u < 4; u++)
                #pragma unroll
                for (int v = 0; v < 4; v++)
                    acc[u][v] += av[u] * bv[v];
        }
    }

    float4* G4 = (float4*)g_G;
    #pragma unroll
    for (int u = 0; u < 4; u++) {
        const int i = i0 + 4 * ty + u;
        G4[(i * NTP + j0) / 4 + tx] = make_float4(acc[u][0], acc[u][1], acc[u][2], acc[u][3]);
    }
}

// ---------------------------------------------------------------------------
// Kernel 2: main — warp per batch, no block syncs
// ---------------------------------------------------------------------------
__global__ void __launch_bounds__(256) main_kernel(
    const int* __restrict__ venue, const int* __restrict__ team,
    const int* __restrict__ opp,   const int* __restrict__ result,
    const float* __restrict__ gf,  const float* __restrict__ ga,
    const float* __restrict__ stats,
    const int* __restrict__ next_venue, const int* __restrict__ next_team,
    const int* __restrict__ next_opp,
    const float* __restrict__ W, const float* __restrict__ b_out,
    float* __restrict__ out) {

    const int lane = threadIdx.x & 31;
    const int w    = threadIdx.x >> 5;
    const int b    = blockIdx.x * 8 + w;

    const int nv = next_venue[b];
    const int nt = next_team[b];
    const int no = next_opp[b];
    const float* __restrict__ Gnt = g_G + nt * NTP;   // L1-resident row
    const float* __restrict__ Gno = g_G + no * NTP;

    int   vv[8], tt[8], oo[8], rr[8];
    float gfv[8], gav[8], s[8];

    const int base = b * L + lane;
    #pragma unroll
    for (int j = 0; j < 8; j++) {
        const int idx = base + 32 * j;
        vv[j]  = venue[idx];
        tt[j]  = team[idx];
        oo[j]  = opp[idx];
        rr[j]  = result[idx];
        gfv[j] = gf[idx];
        gav[j] = ga[idx];
    }

    const float inv_scale = 0.051031036307982884f;  // 1/sqrt(384)
    #pragma unroll
    for (int j = 0; j < 8; j++)
        s[j] = (g_Gven[vv[j] * 3 + nv] + Gnt[tt[j]] + Gno[oo[j]]) * inv_scale;

    // warp softmax
    float m = s[0];
    #pragma unroll
    for (int j = 1; j < 8; j++) m = fmaxf(m, s[j]);
    #pragma unroll
    for (int off = 16; off; off >>= 1)
        m = fmaxf(m, __shfl_xor_sync(0xffffffffu, m, off));

    float e[8], su = 0.0f;
    #pragma unroll
    for (int j = 0; j < 8; j++) { e[j] = __expf(s[j] - m); su += e[j]; }
    #pragma unroll
    for (int off = 16; off; off >>= 1)
        su += __shfl_xor_sync(0xffffffffu, su, off);
    const float inv = __frcp_rn(su);

    const float wgf0 = W[512 * 3 + 0], wgf1 = W[512 * 3 + 1], wgf2 = W[512 * 3 + 2];
    const float wga0 = W[513 * 3 + 0], wga1 = W[513 * 3 + 1], wga2 = W[513 * 3 + 2];

    float c0 = 0, c1 = 0, c2 = 0;
    #pragma unroll
    for (int j = 0; j < 8; j++) {
        const float a = e[j] * inv;
        const float4 p1  = g_PT1[tt[j]];
        const float4 p2  = g_PT2[oo[j]];
        const float4 pvr = g_PVR[vv[j] * 3 + rr[j]];
        c0 += a * (p1.x + p2.x + pvr.x + gfv[j] * wgf0 + gav[j] * wga0);
        c1 += a * (p1.y + p2.y + pvr.y + gfv[j] * wgf1 + gav[j] * wga1);
        c2 += a * (p1.z + p2.z + pvr.z + gfv[j] * wgf2 + gav[j] * wga2);
    }
    #pragma unroll
    for (int off = 16; off; off >>= 1) {
        c0 += __shfl_xor_sync(0xffffffffu, c0, off);
        c1 += __shfl_xor_sync(0xffffffffu, c1, off);
        c2 += __shfl_xor_sync(0xffffffffu, c2, off);
    }

    if (lane == 0) {
        const float s0 = stats[b * 3 + 0], s1 = stats[b * 3 + 1], s2 = stats[b * 3 + 2];
        c0 += s0 * W[514 * 3 + 0] + s1 * W[515 * 3 + 0] + s2 * W[516 * 3 + 0] + b_out[0];
        c1 += s0 * W[514 * 3 + 1] + s1 * W[515 * 3 + 1] + s2 * W[516 * 3 + 1] + b_out[1];
        c2 += s0 * W[514 * 3 + 2] + s1 * W[515 * 3 + 2] + s2 * W[516 * 3 + 2] + b_out[2];
        out[b * 3 + 0] = c0;
        out[b * 3 + 1] = c1;
        out[b * 3 + 2] = c2;
    }
}

// ---------------------------------------------------------------------------
extern "C" void kernel_launch(void* const* d_in, const int* in_sizes, int n_in,
                              void* d_out, int out_size) {
    const float* team_embed    = (const float*)d_in[0];
    const float* venue_embed   = (const float*)d_in[1];
    const float* result_embed  = (const float*)d_in[2];
    const float* W_out         = (const float*)d_in[3];
    const float* b_out         = (const float*)d_in[4];
    const float* goals_for     = (const float*)d_in[5];
    const float* goals_against = (const float*)d_in[6];
    const float* stats         = (const float*)d_in[7];
    const int*   venue         = (const int*)d_in[8];
    const int*   team          = (const int*)d_in[9];
    const int*   opponent      = (const int*)d_in[10];
    const int*   result        = (const int*)d_in[11];
    const int*   next_venue    = (const int*)d_in[12];
    const int*   next_team     = (const int*)d_in[13];
    const int*   next_opponent = (const int*)d_in[14];
    float* out = (float*)d_out;

    prep_kernel<<<132, 256>>>(team_embed, venue_embed, result_embed, W_out);

    gram_kernel<<<dim3(16, 16), 256>>>();

    main_kernel<<<128, 256>>>(venue, team, opponent, result,
                              goals_for, goals_against, stats,
                              next_venue, next_team, next_opponent,
                              W_out, b_out, out);
}

// round 4
// speedup vs baseline: 3.8839x; 2.1584x over previous
#include <cuda_runtime.h>
#include <math.h>

#define NT   1000
#define NTP  1024
#define H    128
#define B    1024
#define L    256
#define NTILE 16            // 1024/64
#define NPAIR (NTILE*(NTILE+1)/2)   // 136 lower-triangle tiles
// W_out (517,3) row-major: rows 0:128 venue, 128:256 team, 256:384 opp,
// 384:512 result, 512 gf, 513 ga, 514:517 stats.

// ---- device scratch ----
__device__ float  g_G[NTP * NTP];   // team Gram
__device__ float4 g_PT1[NTP];       // team_embed @ W[128:256]
__device__ float4 g_PT2[NTP];       // team_embed @ W[256:384]
__device__ float4 g_PVR[9];         // PV[v]+PR[r] fused
__device__ float  g_Gven[9];        // venue Gram

// ---------------------------------------------------------------------------
// Kernel 1 (fused): blocks 0..135 gram tiles (symmetric), 136..139 team proj,
// block 140 the 3x3 tables.
// ---------------------------------------------------------------------------
__global__ void __launch_bounds__(256) prep_gram_kernel(
    const float* __restrict__ E,            // team_embed
    const float* __restrict__ venue_embed,
    const float* __restrict__ result_embed,
    const float* __restrict__ W) {
    const int bx  = blockIdx.x;
    const int tid = threadIdx.x;

    if (bx < NPAIR) {
        // ---- symmetric gram tile ----
        __shared__ float As[64 * 68];
        __shared__ float Bs[64 * 68];
        // lower-triangle decode: ti >= tj
        const int ti = (int)floorf((sqrtf(8.0f * bx + 1.0f) - 1.0f) * 0.5f + 1e-4f);
        const int tj = bx - ti * (ti + 1) / 2;
        const int i0 = ti * 64;
        const int j0 = tj * 64;
        const int tx = tid & 15;
        const int ty = tid >> 4;

        float acc[4][4];
        #pragma unroll
        for (int u = 0; u < 4; u++)
            #pragma unroll
            for (int v = 0; v < 4; v++) acc[u][v] = 0.0f;

        const float4 z4 = make_float4(0.f, 0.f, 0.f, 0.f);
        for (int kb = 0; kb < H; kb += 64) {
            __syncthreads();
            #pragma unroll
            for (int i = 0; i < 4; i++) {
                const int idx = tid + 256 * i;
                const int t  = idx >> 4;      // 0..63 local team
                const int k4 = idx & 15;      // float4 index along k
                const int ri = i0 + t;
                const int rj = j0 + t;
                const float4 a = (ri < NT) ? *(const float4*)(E + ri * H + kb + 4 * k4) : z4;
                const float4 b = (rj < NT) ? *(const float4*)(E + rj * H + kb + 4 * k4) : z4;
                const int c = t ^ (4 * (k4 & 7));     // swizzled scalar column
                const int r0 = 4 * k4;
                As[(r0 + 0) * 68 + c] = a.x;
                As[(r0 + 1) * 68 + c] = a.y;
                As[(r0 + 2) * 68 + c] = a.z;
                As[(r0 + 3) * 68 + c] = a.w;
                Bs[(r0 + 0) * 68 + c] = b.x;
                Bs[(r0 + 1) * 68 + c] = b.y;
                Bs[(r0 + 2) * 68 + c] = b.z;
                Bs[(r0 + 3) * 68 + c] = b.w;
            }
            __syncthreads();

            #pragma unroll 16
            for (int k = 0; k < 64; k++) {
                const int cc = (k >> 2) & 7;
                const float4 a4 = *(const float4*)&As[k * 68 + 4 * (ty ^ cc)];
                const float4 b4 = *(const float4*)&Bs[k * 68 + 4 * (tx ^ cc)];
                const float av[4] = {a4.x, a4.y, a4.z, a4.w};
                const float bv[4] = {b4.x, b4.y, b4.z, b4.w};
                #pragma unroll
                for (int u = 0; u < 4; u++)
                    #pragma unroll
                    for (int v = 0; v < 4; v++)
                        acc[u][v] += av[u] * bv[v];
            }
        }

        float4* G4 = (float4*)g_G;
        #pragma unroll
        for (int u = 0; u < 4; u++) {
            const int i = i0 + 4 * ty + u;
            G4[(i * NTP + j0) / 4 + tx] =
                make_float4(acc[u][0], acc[u][1], acc[u][2], acc[u][3]);
        }
        if (ti != tj) {
            #pragma unroll
            for (int v = 0; v < 4; v++) {
                const int j = j0 + 4 * tx + v;
                G4[(j * NTP + i0) / 4 + ty] =
                    make_float4(acc[0][v], acc[1][v], acc[2][v], acc[3][v]);
            }
        }
        return;
    }

    if (bx < NPAIR + 4) {
        // ---- team projections ----
        const int t = (bx - NPAIR) * 256 + tid;
        if (t < NT) {
            const float4* row = (const float4*)(E + t * H);
            float a0 = 0, a1 = 0, a2 = 0, b0 = 0, b1 = 0, b2 = 0;
            #pragma unroll 8
            for (int k4 = 0; k4 < 32; k4++) {
                const float4 e = row[k4];
                const float ev[4] = {e.x, e.y, e.z, e.w};
                #pragma unroll
                for (int d = 0; d < 4; d++) {
                    const int k = 4 * k4 + d;
                    a0 += ev[d] * W[(128 + k) * 3 + 0];
                    a1 += ev[d] * W[(128 + k) * 3 + 1];
                    a2 += ev[d] * W[(128 + k) * 3 + 2];
                    b0 += ev[d] * W[(256 + k) * 3 + 0];
                    b1 += ev[d] * W[(256 + k) * 3 + 1];
                    b2 += ev[d] * W[(256 + k) * 3 + 2];
                }
            }
            g_PT1[t] = make_float4(a0, a1, a2, 0.0f);
            g_PT2[t] = make_float4(b0, b1, b2, 0.0f);
        }
        return;
    }

    // ---- 3x3 tables: one warp per (i,j) pair, k split across lanes ----
    {
        const int w    = tid >> 5;
        const int lane = tid & 31;
        for (int p = w; p < 9; p += 8) {
            const int i = p / 3, j = p % 3;
            // 4 k-values per lane
            const float4 vi = *(const float4*)(venue_embed  + i * H + 4 * lane);
            const float4 vj = *(const float4*)(venue_embed  + j * H + 4 * lane);
            const float4 re = *(const float4*)(result_embed + j * H + 4 * lane);
            // W rows 4*lane..4*lane+3 of head block and result block (12 floats each)
            const float4 w0 = *(const float4*)(W + 12 * lane + 0);
            const float4 w1 = *(const float4*)(W + 12 * lane + 4);
            const float4 w2 = *(const float4*)(W + 12 * lane + 8);
            const float4 q0 = *(const float4*)(W + 384 * 3 + 12 * lane + 0);
            const float4 q1 = *(const float4*)(W + 384 * 3 + 12 * lane + 4);
            const float4 q2 = *(const float4*)(W + 384 * 3 + 12 * lane + 8);
            const float viv[4] = {vi.x, vi.y, vi.z, vi.w};
            const float vjv[4] = {vj.x, vj.y, vj.z, vj.w};
            const float rev[4] = {re.x, re.y, re.z, re.w};
            const float wv[12] = {w0.x, w0.y, w0.z, w0.w, w1.x, w1.y, w1.z, w1.w,
                                  w2.x, w2.y, w2.z, w2.w};
            const float qv[12] = {q0.x, q0.y, q0.z, q0.w, q1.x, q1.y, q1.z, q1.w,
                                  q2.x, q2.y, q2.z, q2.w};
            float gv = 0, p0 = 0, p1 = 0, p2 = 0;
            #pragma unroll
            for (int d = 0; d < 4; d++) {
                gv += viv[d] * vjv[d];
                p0 += viv[d] * wv[3 * d + 0] + rev[d] * qv[3 * d + 0];
                p1 += viv[d] * wv[3 * d + 1] + rev[d] * qv[3 * d + 1];
                p2 += viv[d] * wv[3 * d + 2] + rev[d] * qv[3 * d + 2];
            }
            #pragma unroll
            for (int off = 16; off; off >>= 1) {
                gv += __shfl_xor_sync(0xffffffffu, gv, off);
                p0 += __shfl_xor_sync(0xffffffffu, p0, off);
                p1 += __shfl_xor_sync(0xffffffffu, p1, off);
                p2 += __shfl_xor_sync(0xffffffffu, p2, off);
            }
            if (lane == 0) {
                g_Gven[p] = gv;                 // venue_i . venue_j
                g_PVR[p]  = make_float4(p0, p1, p2, 0.0f);  // (i=venue, j=result)
            }
        }
    }
}

// ---------------------------------------------------------------------------
// Kernel 2: main — warp per batch
// ---------------------------------------------------------------------------
__global__ void __launch_bounds__(256) main_kernel(
    const int* __restrict__ venue, const int* __restrict__ team,
    const int* __restrict__ opp,   const int* __restrict__ result,
    const float* __restrict__ gf,  const float* __restrict__ ga,
    const float* __restrict__ stats,
    const int* __restrict__ next_venue, const int* __restrict__ next_team,
    const int* __restrict__ next_opp,
    const float* __restrict__ W, const float* __restrict__ b_out,
    float* __restrict__ out) {

    const int lane = threadIdx.x & 31;
    const int w    = threadIdx.x >> 5;
    const int b    = blockIdx.x * 8 + w;

    const int nv = next_venue[b];
    const int nt = next_team[b];
    const int no = next_opp[b];
    const float* __restrict__ Gnt = g_G + nt * NTP;
    const float* __restrict__ Gno = g_G + no * NTP;

    int   vv[8], tt[8], oo[8], rr[8];
    float gfv[8], gav[8], s[8];

    const int base = b * L + lane;
    #pragma unroll
    for (int j = 0; j < 8; j++) {
        const int idx = base + 32 * j;
        vv[j]  = venue[idx];
        tt[j]  = team[idx];
        oo[j]  = opp[idx];
        rr[j]  = result[idx];
        gfv[j] = gf[idx];
        gav[j] = ga[idx];
    }

    const float inv_scale = 0.051031036307982884f;  // 1/sqrt(384)
    #pragma unroll
    for (int j = 0; j < 8; j++)
        s[j] = (g_Gven[vv[j] * 3 + nv] + Gnt[tt[j]] + Gno[oo[j]]) * inv_scale;

    float m = s[0];
    #pragma unroll
    for (int j = 1; j < 8; j++) m = fmaxf(m, s[j]);
    #pragma unroll
    for (int off = 16; off; off >>= 1)
        m = fmaxf(m, __shfl_xor_sync(0xffffffffu, m, off));

    float e[8], su = 0.0f;
    #pragma unroll
    for (int j = 0; j < 8; j++) { e[j] = __expf(s[j] - m); su += e[j]; }
    #pragma unroll
    for (int off = 16; off; off >>= 1)
        su += __shfl_xor_sync(0xffffffffu, su, off);
    const float inv = __frcp_rn(su);

    const float wgf0 = W[512 * 3 + 0], wgf1 = W[512 * 3 + 1], wgf2 = W[512 * 3 + 2];
    const float wga0 = W[513 * 3 + 0], wga1 = W[513 * 3 + 1], wga2 = W[513 * 3 + 2];

    float c0 = 0, c1 = 0, c2 = 0;
    #pragma unroll
    for (int j = 0; j < 8; j++) {
        const float a = e[j] * inv;
        const float4 p1  = g_PT1[tt[j]];
        const float4 p2  = g_PT2[oo[j]];
        const float4 pvr = g_PVR[vv[j] * 3 + rr[j]];
        c0 += a * (p1.x + p2.x + pvr.x + gfv[j] * wgf0 + gav[j] * wga0);
        c1 += a * (p1.y + p2.y + pvr.y + gfv[j] * wgf1 + gav[j] * wga1);
        c2 += a * (p1.z + p2.z + pvr.z + gfv[j] * wgf2 + gav[j] * wga2);
    }
    #pragma unroll
    for (int off = 16; off; off >>= 1) {
        c0 += __shfl_xor_sync(0xffffffffu, c0, off);
        c1 += __shfl_xor_sync(0xffffffffu, c1, off);
        c2 += __shfl_xor_sync(0xffffffffu, c2, off);
    }

    if (lane == 0) {
        const float s0 = stats[b * 3 + 0], s1 = stats[b * 3 + 1], s2 = stats[b * 3 + 2];
        c0 += s0 * W[514 * 3 + 0] + s1 * W[515 * 3 + 0] + s2 * W[516 * 3 + 0] + b_out[0];
        c1 += s0 * W[514 * 3 + 1] + s1 * W[515 * 3 + 1] + s2 * W[516 * 3 + 1] + b_out[1];
        c2 += s0 * W[514 * 3 + 2] + s1 * W[515 * 3 + 2] + s2 * W[516 * 3 + 2] + b_out[2];
        out[b * 3 + 0] = c0;
        out[b * 3 + 1] = c1;
        out[b * 3 + 2] = c2;
    }
}

// ---------------------------------------------------------------------------
extern "C" void kernel_launch(void* const* d_in, const int* in_sizes, int n_in,
                              void* d_out, int out_size) {
    const float* team_embed    = (const float*)d_in[0];
    const float* venue_embed   = (const float*)d_in[1];
    const float* result_embed  = (const float*)d_in[2];
    const float* W_out         = (const float*)d_in[3];
    const float* b_out         = (const float*)d_in[4];
    const float* goals_for     = (const float*)d_in[5];
    const float* goals_against = (const float*)d_in[6];
    const float* stats         = (const float*)d_in[7];
    const int*   venue         = (const int*)d_in[8];
    const int*   team          = (const int*)d_in[9];
    const int*   opponent      = (const int*)d_in[10];
    const int*   result        = (const int*)d_in[11];
    const int*   next_venue    = (const int*)d_in[12];
    const int*   next_team     = (const int*)d_in[13];
    const int*   next_opponent = (const int*)d_in[14];
    float* out = (float*)d_out;

    prep_gram_kernel<<<NPAIR + 5, 256>>>(team_embed, venue_embed,
                                         result_embed, W_out);

    main_kernel<<<128, 256>>>(venue, team, opponent, result,
                              goals_for, goals_against, stats,
                              next_venue, next_team, next_opponent,
                              W_out, b_out, out);
}

// round 5
// speedup vs baseline: 3.9313x; 1.0122x over previous
#include <cuda_runtime.h>
#include <math.h>

#define NT   1000
#define NTP  1024
#define H    128
#define B    1024
#define L    256
#define NTILE 16
#define NPAIR (NTILE*(NTILE+1)/2)   // 136 lower-triangle 64x64 tiles
// W_out (517,3) row-major: rows 0:128 venue, 128:256 team, 256:384 opp,
// 384:512 result, 512 gf, 513 ga, 514:517 stats.

// ---- device scratch ----
__device__ float  g_G[NTP * NTP];
__device__ float4 g_PT1[NTP];
__device__ float4 g_PT2[NTP];
__device__ float4 g_PVR[9];
__device__ float  g_Gven[9];
__device__ float  g_sink;          // prefetch DCE guard

// ---------------------------------------------------------------------------
// Kernel 1 (fused, grid = 148 = one wave):
//   blocks 0..135   : symmetric gram tiles (f32x2 packed FMA)
//   blocks 136..139 : team projections
//   block  140      : 3x3 tables
//   blocks 141..147 : L2 prefetch of main_kernel's input streams
// ---------------------------------------------------------------------------
__global__ void __launch_bounds__(256) prep_gram_kernel(
    const float* __restrict__ E,
    const float* __restrict__ venue_embed,
    const float* __restrict__ result_embed,
    const float* __restrict__ W,
    const int* __restrict__ venue, const int* __restrict__ team,
    const int* __restrict__ opp,   const int* __restrict__ result,
    const float* __restrict__ gf,  const float* __restrict__ ga) {
    const int bx  = blockIdx.x;
    const int tid = threadIdx.x;

    if (bx < NPAIR) {
        __shared__ float As[64 * 68];
        __shared__ float Bs[64 * 68];
        const int ti = (int)floorf((sqrtf(8.0f * bx + 1.0f) - 1.0f) * 0.5f + 1e-4f);
        const int tj = bx - ti * (ti + 1) / 2;
        const int i0 = ti * 64;
        const int j0 = tj * 64;
        const int tx = tid & 15;
        const int ty = tid >> 4;

        // packed accumulators: accp[u][p] = (acc[u][2p], acc[u][2p+1])
        unsigned long long accp[4][2];
        #pragma unroll
        for (int u = 0; u < 4; u++) { accp[u][0] = 0ull; accp[u][1] = 0ull; }

        const float4 z4 = make_float4(0.f, 0.f, 0.f, 0.f);
        for (int kb = 0; kb < H; kb += 64) {
            __syncthreads();
            #pragma unroll
            for (int i = 0; i < 4; i++) {
                const int idx = tid + 256 * i;
                const int t  = idx >> 4;
                const int k4 = idx & 15;
                const int ri = i0 + t;
                const int rj = j0 + t;
                const float4 a = (ri < NT) ? *(const float4*)(E + ri * H + kb + 4 * k4) : z4;
                const float4 b = (rj < NT) ? *(const float4*)(E + rj * H + kb + 4 * k4) : z4;
                const int c  = t ^ (4 * (k4 & 7));
                const int r0 = 4 * k4;
                As[(r0 + 0) * 68 + c] = a.x;
                As[(r0 + 1) * 68 + c] = a.y;
                As[(r0 + 2) * 68 + c] = a.z;
                As[(r0 + 3) * 68 + c] = a.w;
                Bs[(r0 + 0) * 68 + c] = b.x;
                Bs[(r0 + 1) * 68 + c] = b.y;
                Bs[(r0 + 2) * 68 + c] = b.z;
                Bs[(r0 + 3) * 68 + c] = b.w;
            }
            __syncthreads();

            #pragma unroll 16
            for (int k = 0; k < 64; k++) {
                const int cc = (k >> 2) & 7;
                const float4 a4 = *(const float4*)&As[k * 68 + 4 * (ty ^ cc)];
                const ulonglong2 b2 = *(const ulonglong2*)&Bs[k * 68 + 4 * (tx ^ cc)];
                const unsigned int au[4] = {
                    __float_as_uint(a4.x), __float_as_uint(a4.y),
                    __float_as_uint(a4.z), __float_as_uint(a4.w)};
                #pragma unroll
                for (int u = 0; u < 4; u++) {
                    unsigned long long ap;
                    asm("mov.b64 %0, {%1, %1};" : "=l"(ap) : "r"(au[u]));
                    asm("fma.rn.f32x2 %0, %1, %2, %0;"
                        : "+l"(accp[u][0]) : "l"(ap), "l"(b2.x));
                    asm("fma.rn.f32x2 %0, %1, %2, %0;"
                        : "+l"(accp[u][1]) : "l"(ap), "l"(b2.y));
                }
            }
        }

        // unpack
        float acc[4][4];
        #pragma unroll
        for (int u = 0; u < 4; u++) {
            unsigned int lo, hi;
            asm("mov.b64 {%0, %1}, %2;" : "=r"(lo), "=r"(hi) : "l"(accp[u][0]));
            acc[u][0] = __uint_as_float(lo); acc[u][1] = __uint_as_float(hi);
            asm("mov.b64 {%0, %1}, %2;" : "=r"(lo), "=r"(hi) : "l"(accp[u][1]));
            acc[u][2] = __uint_as_float(lo); acc[u][3] = __uint_as_float(hi);
        }

        float4* G4 = (float4*)g_G;
        #pragma unroll
        for (int u = 0; u < 4; u++) {
            const int i = i0 + 4 * ty + u;
            G4[(i * NTP + j0) / 4 + tx] =
                make_float4(acc[u][0], acc[u][1], acc[u][2], acc[u][3]);
        }
        if (ti != tj) {
            #pragma unroll
            for (int v = 0; v < 4; v++) {
                const int j = j0 + 4 * tx + v;
                G4[(j * NTP + i0) / 4 + ty] =
                    make_float4(acc[0][v], acc[1][v], acc[2][v], acc[3][v]);
            }
        }
        return;
    }

    if (bx < NPAIR + 4) {
        const int t = (bx - NPAIR) * 256 + tid;
        if (t < NT) {
            const float4* row = (const float4*)(E + t * H);
            float a0 = 0, a1 = 0, a2 = 0, b0 = 0, b1 = 0, b2 = 0;
            #pragma unroll 8
            for (int k4 = 0; k4 < 32; k4++) {
                const float4 e = row[k4];
                const float ev[4] = {e.x, e.y, e.z, e.w};
                #pragma unroll
                for (int d = 0; d < 4; d++) {
                    const int k = 4 * k4 + d;
                    a0 += ev[d] * W[(128 + k) * 3 + 0];
                    a1 += ev[d] * W[(128 + k) * 3 + 1];
                    a2 += ev[d] * W[(128 + k) * 3 + 2];
                    b0 += ev[d] * W[(256 + k) * 3 + 0];
                    b1 += ev[d] * W[(256 + k) * 3 + 1];
                    b2 += ev[d] * W[(256 + k) * 3 + 2];
                }
            }
            g_PT1[t] = make_float4(a0, a1, a2, 0.0f);
            g_PT2[t] = make_float4(b0, b1, b2, 0.0f);
        }
        return;
    }

    if (bx == NPAIR + 4) {
        // 3x3 tables: warp per (i,j)
        const int w    = tid >> 5;
        const int lane = tid & 31;
        for (int p = w; p < 9; p += 8) {
            const int i = p / 3, j = p % 3;
            const float4 vi = *(const float4*)(venue_embed  + i * H + 4 * lane);
            const float4 vj = *(const float4*)(venue_embed  + j * H + 4 * lane);
            const float4 re = *(const float4*)(result_embed + j * H + 4 * lane);
            const float4 w0 = *(const float4*)(W + 12 * lane + 0);
            const float4 w1 = *(const float4*)(W + 12 * lane + 4);
            const float4 w2 = *(const float4*)(W + 12 * lane + 8);
            const float4 q0 = *(const float4*)(W + 384 * 3 + 12 * lane + 0);
            const float4 q1 = *(const float4*)(W + 384 * 3 + 12 * lane + 4);
            const float4 q2 = *(const float4*)(W + 384 * 3 + 12 * lane + 8);
            const float viv[4] = {vi.x, vi.y, vi.z, vi.w};
            const float vjv[4] = {vj.x, vj.y, vj.z, vj.w};
            const float rev[4] = {re.x, re.y, re.z, re.w};
            const float wv[12] = {w0.x, w0.y, w0.z, w0.w, w1.x, w1.y, w1.z, w1.w,
                                  w2.x, w2.y, w2.z, w2.w};
            const float qv[12] = {q0.x, q0.y, q0.z, q0.w, q1.x, q1.y, q1.z, q1.w,
                                  q2.x, q2.y, q2.z, q2.w};
            float gv = 0, p0 = 0, p1 = 0, p2 = 0;
            #pragma unroll
            for (int d = 0; d < 4; d++) {
                gv += viv[d] * vjv[d];
                p0 += viv[d] * wv[3 * d + 0] + rev[d] * qv[3 * d + 0];
                p1 += viv[d] * wv[3 * d + 1] + rev[d] * qv[3 * d + 1];
                p2 += viv[d] * wv[3 * d + 2] + rev[d] * qv[3 * d + 2];
            }
            #pragma unroll
            for (int off = 16; off; off >>= 1) {
                gv += __shfl_xor_sync(0xffffffffu, gv, off);
                p0 += __shfl_xor_sync(0xffffffffu, p0, off);
                p1 += __shfl_xor_sync(0xffffffffu, p1, off);
                p2 += __shfl_xor_sync(0xffffffffu, p2, off);
            }
            if (lane == 0) {
                g_Gven[p] = gv;
                g_PVR[p]  = make_float4(p0, p1, p2, 0.0f);
            }
        }
        return;
    }

    // ---- L2 prefetch of main inputs (blocks 141..147) ----
    {
        const int pid = bx - (NPAIR + 5);           // 0..6
        const int NF4 = (B * L) / 4;                // 65536 float4 per array
        const float4* srcs[6] = {
            (const float4*)venue, (const float4*)team, (const float4*)opp,
            (const float4*)result, (const float4*)gf, (const float4*)ga};
        float acc = 0.0f;
        for (int i = pid * 256 + tid; i < 6 * NF4; i += 7 * 256) {
            const float4 v = srcs[i >> 16][i & (NF4 - 1)];
            acc += v.x + v.y + v.z + v.w;
        }
        if (acc == 1.2345e30f) g_sink = acc;  // never true; defeats DCE
    }
}

// ---------------------------------------------------------------------------
// Kernel 2: main — 2 warps per batch, 4 batches per block, grid 256
// ---------------------------------------------------------------------------
__global__ void __launch_bounds__(256) main_kernel(
    const int* __restrict__ venue, const int* __restrict__ team,
    const int* __restrict__ opp,   const int* __restrict__ result,
    const float* __restrict__ gf,  const float* __restrict__ ga,
    const float* __restrict__ stats,
    const int* __restrict__ next_venue, const int* __restrict__ next_team,
    const int* __restrict__ next_opp,
    const float* __restrict__ W, const float* __restrict__ b_out,
    float* __restrict__ out) {

    __shared__ float red_m[8];
    __shared__ float red_s[8];
    __shared__ float red_c[8][3];

    const int lane = threadIdx.x & 31;
    const int w    = threadIdx.x >> 5;
    const int b    = blockIdx.x * 4 + (w >> 1);
    const int half = w & 1;

    const int nv = next_venue[b];
    const int nt = next_team[b];
    const int no = next_opp[b];
    const float* __restrict__ Gnt = g_G + nt * NTP;
    const float* __restrict__ Gno = g_G + no * NTP;

    const int idx0 = b * L + half * 128 + lane * 4;
    const int4   v4  = *(const int4*)(venue  + idx0);
    const int4   t4  = *(const int4*)(team   + idx0);
    const int4   o4  = *(const int4*)(opp    + idx0);
    const int4   r4  = *(const int4*)(result + idx0);
    const float4 gf4 = *(const float4*)(gf + idx0);
    const float4 ga4 = *(const float4*)(ga + idx0);

    const int   vv[4]  = {v4.x, v4.y, v4.z, v4.w};
    const int   tt[4]  = {t4.x, t4.y, t4.z, t4.w};
    const int   oo[4]  = {o4.x, o4.y, o4.z, o4.w};
    const int   rr[4]  = {r4.x, r4.y, r4.z, r4.w};
    const float gfv[4] = {gf4.x, gf4.y, gf4.z, gf4.w};
    const float gav[4] = {ga4.x, ga4.y, ga4.z, ga4.w};

    const float inv_scale = 0.051031036307982884f;  // 1/sqrt(384)
    float s[4];
    #pragma unroll
    for (int j = 0; j < 4; j++)
        s[j] = (g_Gven[vv[j] * 3 + nv] + Gnt[tt[j]] + Gno[oo[j]]) * inv_scale;

    // warp-local max
    float m = fmaxf(fmaxf(s[0], s[1]), fmaxf(s[2], s[3]));
    #pragma unroll
    for (int off = 16; off; off >>= 1)
        m = fmaxf(m, __shfl_xor_sync(0xffffffffu, m, off));
    if (lane == 0) red_m[w] = m;
    __syncthreads();
    m = fmaxf(red_m[w], red_m[w ^ 1]);

    float e[4], su = 0.0f;
    #pragma unroll
    for (int j = 0; j < 4; j++) { e[j] = __expf(s[j] - m); su += e[j]; }
    #pragma unroll
    for (int off = 16; off; off >>= 1)
        su += __shfl_xor_sync(0xffffffffu, su, off);
    if (lane == 0) red_s[w] = su;
    __syncthreads();
    const float inv = __frcp_rn(red_s[w] + red_s[w ^ 1]);

    const float wgf0 = W[512 * 3 + 0], wgf1 = W[512 * 3 + 1], wgf2 = W[512 * 3 + 2];
    const float wga0 = W[513 * 3 + 0], wga1 = W[513 * 3 + 1], wga2 = W[513 * 3 + 2];

    float c0 = 0, c1 = 0, c2 = 0;
    #pragma unroll
    for (int j = 0; j < 4; j++) {
        const float a = e[j] * inv;
        const float4 p1  = g_PT1[tt[j]];
        const float4 p2  = g_PT2[oo[j]];
        const float4 pvr = g_PVR[vv[j] * 3 + rr[j]];
        c0 += a * (p1.x + p2.x + pvr.x + gfv[j] * wgf0 + gav[j] * wga0);
        c1 += a * (p1.y + p2.y + pvr.y + gfv[j] * wgf1 + gav[j] * wga1);
        c2 += a * (p1.z + p2.z + pvr.z + gfv[j] * wgf2 + gav[j] * wga2);
    }
    #pragma unroll
    for (int off = 16; off; off >>= 1) {
        c0 += __shfl_xor_sync(0xffffffffu, c0, off);
        c1 += __shfl_xor_sync(0xffffffffu, c1, off);
        c2 += __shfl_xor_sync(0xffffffffu, c2, off);
    }
    if (lane == 0) {
        red_c[w][0] = c0; red_c[w][1] = c1; red_c[w][2] = c2;
    }
    __syncthreads();

    if (half == 0 && lane == 0) {
        c0 = red_c[w][0] + red_c[w + 1][0];
        c1 = red_c[w][1] + red_c[w + 1][1];
        c2 = red_c[w][2] + red_c[w + 1][2];
        const float s0 = stats[b * 3 + 0], s1 = stats[b * 3 + 1], s2 = stats[b * 3 + 2];
        c0 += s0 * W[514 * 3 + 0] + s1 * W[515 * 3 + 0] + s2 * W[516 * 3 + 0] + b_out[0];
        c1 += s0 * W[514 * 3 + 1] + s1 * W[515 * 3 + 1] + s2 * W[516 * 3 + 1] + b_out[1];
        c2 += s0 * W[514 * 3 + 2] + s1 * W[515 * 3 + 2] + s2 * W[516 * 3 + 2] + b_out[2];
        out[b * 3 + 0] = c0;
        out[b * 3 + 1] = c1;
        out[b * 3 + 2] = c2;
    }
}

// ---------------------------------------------------------------------------
extern "C" void kernel_launch(void* const* d_in, const int* in_sizes, int n_in,
                              void* d_out, int out_size) {
    const float* team_embed    = (const float*)d_in[0];
    const float* venue_embed   = (const float*)d_in[1];
    const float* result_embed  = (const float*)d_in[2];
    const float* W_out         = (const float*)d_in[3];
    const float* b_out         = (const float*)d_in[4];
    const float* goals_for     = (const float*)d_in[5];
    const float* goals_against = (const float*)d_in[6];
    const float* stats         = (const float*)d_in[7];
    const int*   venue         = (const int*)d_in[8];
    const int*   team          = (const int*)d_in[9];
    const int*   opponent      = (const int*)d_in[10];
    const int*   result        = (const int*)d_in[11];
    const int*   next_venue    = (const int*)d_in[12];
    const int*   next_team     = (const int*)d_in[13];
    const int*   next_opponent = (const int*)d_in[14];
    float* out = (float*)d_out;

    prep_gram_kernel<<<NPAIR + 12, 256>>>(team_embed, venue_embed,
                                          result_embed, W_out,
                                          venue, team, opponent, result,
                                          goals_for, goals_against);

    main_kernel<<<256, 256>>>(venue, team, opponent, result,
                              goals_for, goals_against, stats,
                              next_venue, next_team, next_opponent,
                              W_out, b_out, out);
}

// round 6
// speedup vs baseline: 4.3497x; 1.1064x over previous
#include <cuda_runtime.h>
#include <math.h>

#define NT   1000
#define NTP  1024
#define H    128
#define B    1024
#define L    256
#define NTILE 16
#define NPAIR (NTILE*(NTILE+1)/2)   // 136 lower-triangle 64x64 tiles
// W_out (517,3) row-major: rows 0:128 venue, 128:256 team, 256:384 opp,
// 384:512 result, 512 gf, 513 ga, 514:517 stats.

// ---- device scratch ----
__device__ float  g_G[NTP * NTP];
__device__ float4 g_PT1[NTP];
__device__ float4 g_PT2[NTP];
__device__ float4 g_PVR[9];
__device__ float  g_Gven[9];

// ---------------------------------------------------------------------------
// Kernel 1 (fused, grid = 141):
//   blocks 0..135   : symmetric gram tiles (f32x2 FMA, both k-halves preloaded)
//   blocks 136..139 : team projections
//   block  140      : 3x3 tables
// ---------------------------------------------------------------------------
__global__ void __launch_bounds__(256) prep_gram_kernel(
    const float* __restrict__ E,
    const float* __restrict__ venue_embed,
    const float* __restrict__ result_embed,
    const float* __restrict__ W) {
    const int bx  = blockIdx.x;
    const int tid = threadIdx.x;

    if (bx < NPAIR) {
        __shared__ float As[64 * 68];
        __shared__ float Bs[64 * 68];
        const int ti = (int)floorf((sqrtf(8.0f * bx + 1.0f) - 1.0f) * 0.5f + 1e-4f);
        const int tj = bx - ti * (ti + 1) / 2;
        const int i0 = ti * 64;
        const int j0 = tj * 64;
        const int tx = tid & 15;
        const int ty = tid >> 4;

        // preload BOTH k-halves: 16 LDG.128 in flight
        const int t_  = tid >> 4;       // local team row this thread loads
        const int k4_ = tid & 15;       // float4 index along k
        float4 ra[2][4], rb[2][4];
        const float4 z4 = make_float4(0.f, 0.f, 0.f, 0.f);
        #pragma unroll
        for (int h = 0; h < 2; h++) {
            #pragma unroll
            for (int i = 0; i < 4; i++) {
                const int idx = tid + 256 * i;
                const int t  = idx >> 4;
                const int k4 = idx & 15;
                const int ri = i0 + t;
                const int rj = j0 + t;
                ra[h][i] = (ri < NT) ? *(const float4*)(E + ri * H + 64 * h + 4 * k4) : z4;
                rb[h][i] = (rj < NT) ? *(const float4*)(E + rj * H + 64 * h + 4 * k4) : z4;
            }
        }
        (void)t_; (void)k4_;

        unsigned long long accp[4][2];
        #pragma unroll
        for (int u = 0; u < 4; u++) { accp[u][0] = 0ull; accp[u][1] = 0ull; }

        #pragma unroll
        for (int h = 0; h < 2; h++) {
            if (h) __syncthreads();   // protect As/Bs reuse
            #pragma unroll
            for (int i = 0; i < 4; i++) {
                const int idx = tid + 256 * i;
                const int t  = idx >> 4;
                const int k4 = idx & 15;
                const int c  = t ^ (4 * (k4 & 7));
                const int r0 = 4 * k4;
                As[(r0 + 0) * 68 + c] = ra[h][i].x;
                As[(r0 + 1) * 68 + c] = ra[h][i].y;
                As[(r0 + 2) * 68 + c] = ra[h][i].z;
                As[(r0 + 3) * 68 + c] = ra[h][i].w;
                Bs[(r0 + 0) * 68 + c] = rb[h][i].x;
                Bs[(r0 + 1) * 68 + c] = rb[h][i].y;
                Bs[(r0 + 2) * 68 + c] = rb[h][i].z;
                Bs[(r0 + 3) * 68 + c] = rb[h][i].w;
            }
            __syncthreads();

            #pragma unroll 16
            for (int k = 0; k < 64; k++) {
                const int cc = (k >> 2) & 7;
                const float4 a4 = *(const float4*)&As[k * 68 + 4 * (ty ^ cc)];
                const ulonglong2 b2 = *(const ulonglong2*)&Bs[k * 68 + 4 * (tx ^ cc)];
                const unsigned int au[4] = {
                    __float_as_uint(a4.x), __float_as_uint(a4.y),
                    __float_as_uint(a4.z), __float_as_uint(a4.w)};
                #pragma unroll
                for (int u = 0; u < 4; u++) {
                    unsigned long long ap;
                    asm("mov.b64 %0, {%1, %1};" : "=l"(ap) : "r"(au[u]));
                    asm("fma.rn.f32x2 %0, %1, %2, %0;"
                        : "+l"(accp[u][0]) : "l"(ap), "l"(b2.x));
                    asm("fma.rn.f32x2 %0, %1, %2, %0;"
                        : "+l"(accp[u][1]) : "l"(ap), "l"(b2.y));
                }
            }
        }

        float acc[4][4];
        #pragma unroll
        for (int u = 0; u < 4; u++) {
            unsigned int lo, hi;
            asm("mov.b64 {%0, %1}, %2;" : "=r"(lo), "=r"(hi) : "l"(accp[u][0]));
            acc[u][0] = __uint_as_float(lo); acc[u][1] = __uint_as_float(hi);
            asm("mov.b64 {%0, %1}, %2;" : "=r"(lo), "=r"(hi) : "l"(accp[u][1]));
            acc[u][2] = __uint_as_float(lo); acc[u][3] = __uint_as_float(hi);
        }

        float4* G4 = (float4*)g_G;
        #pragma unroll
        for (int u = 0; u < 4; u++) {
            const int i = i0 + 4 * ty + u;
            G4[(i * NTP + j0) / 4 + tx] =
                make_float4(acc[u][0], acc[u][1], acc[u][2], acc[u][3]);
        }
        if (ti != tj) {
            #pragma unroll
            for (int v = 0; v < 4; v++) {
                const int j = j0 + 4 * tx + v;
                G4[(j * NTP + i0) / 4 + ty] =
                    make_float4(acc[0][v], acc[1][v], acc[2][v], acc[3][v]);
            }
        }
        return;
    }

    if (bx < NPAIR + 4) {
        const int t = (bx - NPAIR) * 256 + tid;
        if (t < NT) {
            const float4* row = (const float4*)(E + t * H);
            float a0 = 0, a1 = 0, a2 = 0, b0 = 0, b1 = 0, b2 = 0;
            #pragma unroll 8
            for (int k4 = 0; k4 < 32; k4++) {
                const float4 e = row[k4];
                const float ev[4] = {e.x, e.y, e.z, e.w};
                #pragma unroll
                for (int d = 0; d < 4; d++) {
                    const int k = 4 * k4 + d;
                    a0 += ev[d] * W[(128 + k) * 3 + 0];
                    a1 += ev[d] * W[(128 + k) * 3 + 1];
                    a2 += ev[d] * W[(128 + k) * 3 + 2];
                    b0 += ev[d] * W[(256 + k) * 3 + 0];
                    b1 += ev[d] * W[(256 + k) * 3 + 1];
                    b2 += ev[d] * W[(256 + k) * 3 + 2];
                }
            }
            g_PT1[t] = make_float4(a0, a1, a2, 0.0f);
            g_PT2[t] = make_float4(b0, b1, b2, 0.0f);
        }
        return;
    }

    // 3x3 tables: warp per (i,j)
    {
        const int w    = tid >> 5;
        const int lane = tid & 31;
        for (int p = w; p < 9; p += 8) {
            const int i = p / 3, j = p % 3;
            const float4 vi = *(const float4*)(venue_embed  + i * H + 4 * lane);
            const float4 vj = *(const float4*)(venue_embed  + j * H + 4 * lane);
            const float4 re = *(const float4*)(result_embed + j * H + 4 * lane);
            const float4 w0 = *(const float4*)(W + 12 * lane + 0);
            const float4 w1 = *(const float4*)(W + 12 * lane + 4);
            const float4 w2 = *(const float4*)(W + 12 * lane + 8);
            const float4 q0 = *(const float4*)(W + 384 * 3 + 12 * lane + 0);
            const float4 q1 = *(const float4*)(W + 384 * 3 + 12 * lane + 4);
            const float4 q2 = *(const float4*)(W + 384 * 3 + 12 * lane + 8);
            const float viv[4] = {vi.x, vi.y, vi.z, vi.w};
            const float vjv[4] = {vj.x, vj.y, vj.z, vj.w};
            const float rev[4] = {re.x, re.y, re.z, re.w};
            const float wv[12] = {w0.x, w0.y, w0.z, w0.w, w1.x, w1.y, w1.z, w1.w,
                                  w2.x, w2.y, w2.z, w2.w};
            const float qv[12] = {q0.x, q0.y, q0.z, q0.w, q1.x, q1.y, q1.z, q1.w,
                                  q2.x, q2.y, q2.z, q2.w};
            float gv = 0, p0 = 0, p1 = 0, p2 = 0;
            #pragma unroll
            for (int d = 0; d < 4; d++) {
                gv += viv[d] * vjv[d];
                p0 += viv[d] * wv[3 * d + 0] + rev[d] * qv[3 * d + 0];
                p1 += viv[d] * wv[3 * d + 1] + rev[d] * qv[3 * d + 1];
                p2 += viv[d] * wv[3 * d + 2] + rev[d] * qv[3 * d + 2];
            }
            #pragma unroll
            for (int off = 16; off; off >>= 1) {
                gv += __shfl_xor_sync(0xffffffffu, gv, off);
                p0 += __shfl_xor_sync(0xffffffffu, p0, off);
                p1 += __shfl_xor_sync(0xffffffffu, p1, off);
                p2 += __shfl_xor_sync(0xffffffffu, p2, off);
            }
            if (lane == 0) {
                g_Gven[p] = gv;
                g_PVR[p]  = make_float4(p0, p1, p2, 0.0f);
            }
        }
    }
}

// ---------------------------------------------------------------------------
// Kernel 2: main — warp per batch, smem-staged Gram rows + tables.
// Dynamic smem layout (floats):
//   [0, 16384)         rows[8][2][1024]
//   [16384, 20480)     PT1s  (1024 float4)
//   [20480, 24576)     PT2s  (1024 float4)
//   [24576, 24612)     PVRs  (9 float4)
//   [24612, 24621)     Gvens (9 float)
// ---------------------------------------------------------------------------
#define MAIN_SMEM_BYTES ((24624) * 4)

__global__ void __launch_bounds__(256, 1) main_kernel(
    const int* __restrict__ venue, const int* __restrict__ team,
    const int* __restrict__ opp,   const int* __restrict__ result,
    const float* __restrict__ gf,  const float* __restrict__ ga,
    const float* __restrict__ stats,
    const int* __restrict__ next_venue, const int* __restrict__ next_team,
    const int* __restrict__ next_opp,
    const float* __restrict__ W, const float* __restrict__ b_out,
    float* __restrict__ out) {

    extern __shared__ float sm[];
    float*  rows  = sm;
    float4* PT1s  = (float4*)(sm + 16384);
    float4* PT2s  = (float4*)(sm + 20480);
    float4* PVRs  = (float4*)(sm + 24576);
    float*  Gvens = sm + 24612;

    const int tid  = threadIdx.x;
    const int lane = tid & 31;
    const int w    = tid >> 5;
    const int b    = blockIdx.x * 8 + w;

    const int nv = next_venue[b];
    const int nt = next_team[b];
    const int no = next_opp[b];

    // ---- stage this warp's two Gram rows (coalesced) ----
    const float4* src1 = (const float4*)(g_G + nt * NTP);
    const float4* src2 = (const float4*)(g_G + no * NTP);
    float4* dst1 = (float4*)(rows + w * 2048);
    float4* dst2 = (float4*)(rows + w * 2048 + 1024);
    #pragma unroll
    for (int i = 0; i < 8; i++) {
        dst1[lane + 32 * i] = src1[lane + 32 * i];
        dst2[lane + 32 * i] = src2[lane + 32 * i];
    }
    // ---- stage tables (block-cooperative, coalesced) ----
    #pragma unroll
    for (int i = 0; i < 4; i++) {
        PT1s[tid + 256 * i] = g_PT1[tid + 256 * i];
        PT2s[tid + 256 * i] = g_PT2[tid + 256 * i];
    }
    if (tid < 9) { PVRs[tid] = g_PVR[tid]; Gvens[tid] = g_Gven[tid]; }

    // ---- stream loads: two contiguous 4-groups per thread ----
    const int idx0 = b * L + lane * 4;       // positions lane*4 .. +3
    const int idx1 = idx0 + 128;             // positions 128+lane*4 .. +3
    const int4   v4a  = *(const int4*)(venue  + idx0);
    const int4   t4a  = *(const int4*)(team   + idx0);
    const int4   o4a  = *(const int4*)(opp    + idx0);
    const int4   r4a  = *(const int4*)(result + idx0);
    const float4 gf4a = *(const float4*)(gf + idx0);
    const float4 ga4a = *(const float4*)(ga + idx0);
    const int4   v4b  = *(const int4*)(venue  + idx1);
    const int4   t4b  = *(const int4*)(team   + idx1);
    const int4   o4b  = *(const int4*)(opp    + idx1);
    const int4   r4b  = *(const int4*)(result + idx1);
    const float4 gf4b = *(const float4*)(gf + idx1);
    const float4 ga4b = *(const float4*)(ga + idx1);

    const int   vv[8]  = {v4a.x, v4a.y, v4a.z, v4a.w, v4b.x, v4b.y, v4b.z, v4b.w};
    const int   tt[8]  = {t4a.x, t4a.y, t4a.z, t4a.w, t4b.x, t4b.y, t4b.z, t4b.w};
    const int   oo[8]  = {o4a.x, o4a.y, o4a.z, o4a.w, o4b.x, o4b.y, o4b.z, o4b.w};
    const int   rr[8]  = {r4a.x, r4a.y, r4a.z, r4a.w, r4b.x, r4b.y, r4b.z, r4b.w};
    const float gfv[8] = {gf4a.x, gf4a.y, gf4a.z, gf4a.w, gf4b.x, gf4b.y, gf4b.z, gf4b.w};
    const float gav[8] = {ga4a.x, ga4a.y, ga4a.z, ga4a.w, ga4b.x, ga4b.y, ga4b.z, ga4b.w};

    __syncthreads();

    const float* rw0 = rows + w * 2048;
    const float* rw1 = rows + w * 2048 + 1024;

    const float inv_scale = 0.051031036307982884f;  // 1/sqrt(384)
    float s[8];
    #pragma unroll
    for (int j = 0; j < 8; j++)
        s[j] = (Gvens[vv[j] * 3 + nv] + rw0[tt[j]] + rw1[oo[j]]) * inv_scale;

    // warp softmax (fully warp-local: this warp owns all 256 positions)
    float m = s[0];
    #pragma unroll
    for (int j = 1; j < 8; j++) m = fmaxf(m, s[j]);
    #pragma unroll
    for (int off = 16; off; off >>= 1)
        m = fmaxf(m, __shfl_xor_sync(0xffffffffu, m, off));

    float e[8], su = 0.0f;
    #pragma unroll
    for (int j = 0; j < 8; j++) { e[j] = __expf(s[j] - m); su += e[j]; }
    #pragma unroll
    for (int off = 16; off; off >>= 1)
        su += __shfl_xor_sync(0xffffffffu, su, off);
    const float inv = __frcp_rn(su);

    const float wgf0 = W[512 * 3 + 0], wgf1 = W[512 * 3 + 1], wgf2 = W[512 * 3 + 2];
    const float wga0 = W[513 * 3 + 0], wga1 = W[513 * 3 + 1], wga2 = W[513 * 3 + 2];

    float c0 = 0, c1 = 0, c2 = 0;
    #pragma unroll
    for (int j = 0; j < 8; j++) {
        const float a = e[j] * inv;
        const float4 p1  = PT1s[tt[j]];
        const float4 p2  = PT2s[oo[j]];
        const float4 pvr = PVRs[vv[j] * 3 + rr[j]];
        c0 += a * (p1.x + p2.x + pvr.x + gfv[j] * wgf0 + gav[j] * wga0);
        c1 += a * (p1.y + p2.y + pvr.y + gfv[j] * wgf1 + gav[j] * wga1);
        c2 += a * (p1.z + p2.z + pvr.z + gfv[j] * wgf2 + gav[j] * wga2);
    }
    #pragma unroll
    for (int off = 16; off; off >>= 1) {
        c0 += __shfl_xor_sync(0xffffffffu, c0, off);
        c1 += __shfl_xor_sync(0xffffffffu, c1, off);
        c2 += __shfl_xor_sync(0xffffffffu, c2, off);
    }

    if (lane == 0) {
        const float s0 = stats[b * 3 + 0], s1 = stats[b * 3 + 1], s2 = stats[b * 3 + 2];
        c0 += s0 * W[514 * 3 + 0] + s1 * W[515 * 3 + 0] + s2 * W[516 * 3 + 0] + b_out[0];
        c1 += s0 * W[514 * 3 + 1] + s1 * W[515 * 3 + 1] + s2 * W[516 * 3 + 1] + b_out[1];
        c2 += s0 * W[514 * 3 + 2] + s1 * W[515 * 3 + 2] + s2 * W[516 * 3 + 2] + b_out[2];
        out[b * 3 + 0] = c0;
        out[b * 3 + 1] = c1;
        out[b * 3 + 2] = c2;
    }
}

// ---------------------------------------------------------------------------
extern "C" void kernel_launch(void* const* d_in, const int* in_sizes, int n_in,
                              void* d_out, int out_size) {
    const float* team_embed    = (const float*)d_in[0];
    const float* venue_embed   = (const float*)d_in[1];
    const float* result_embed  = (const float*)d_in[2];
    const float* W_out         = (const float*)d_in[3];
    const float* b_out         = (const float*)d_in[4];
    const float* goals_for     = (const float*)d_in[5];
    const float* goals_against = (const float*)d_in[6];
    const float* stats         = (const float*)d_in[7];
    const int*   venue         = (const int*)d_in[8];
    const int*   team          = (const int*)d_in[9];
    const int*   opponent      = (const int*)d_in[10];
    const int*   result        = (const int*)d_in[11];
    const int*   next_venue    = (const int*)d_in[12];
    const int*   next_team     = (const int*)d_in[13];
    const int*   next_opponent = (const int*)d_in[14];
    float* out = (float*)d_out;

    cudaFuncSetAttribute(main_kernel,
                         cudaFuncAttributeMaxDynamicSharedMemorySize,
                         MAIN_SMEM_BYTES);

    prep_gram_kernel<<<NPAIR + 5, 256>>>(team_embed, venue_embed,
                                         result_embed, W_out);

    main_kernel<<<128, 256, MAIN_SMEM_BYTES>>>(
        venue, team, opponent, result,
        goals_for, goals_against, stats,
        next_venue, next_team, next_opponent,
        W_out, b_out, out);
}